// round 16
// baseline (speedup 1.0000x reference)
#include <cuda_runtime.h>
#include <cstddef>

// Raster_87205015978273: per-depo 10x10x10 Gaussian raster patches.
// Output buffer (all float32): [N*1000] rasters, then [N*3] offsets (exact
// integer values stored as float).
//
// R16: R14 structure (warp-per-depo, shuffle for s=charge*wx[i], __stcs) with
// 256-bit stores: st.global.cs.v8.f32 (sm_100a). 125 float8 per depo in 4
// warp-rounds. Each float8 = two aligned float4 halves (each within one
// x-slab since 100 % 4 == 0), s per half via shuffle.

#define DPB 8        // depos per block: one warp each
#define NTHREADS 256

__device__ __forceinline__ void stg256_cs(float* p, const float4& a, const float4& b)
{
    asm volatile("st.global.cs.v8.f32 [%0], {%1,%2,%3,%4,%5,%6,%7,%8};"
                 :: "l"(p),
                    "f"(a.x), "f"(a.y), "f"(a.z), "f"(a.w),
                    "f"(b.x), "f"(b.y), "f"(b.z), "f"(b.w)
                 : "memory");
}

__global__ __launch_bounds__(NTHREADS, 8)
void raster_kernel(const float* __restrict__ sigma,   // [N,3]
                   const float* __restrict__ time,    // [N]
                   const float* __restrict__ charge,  // [N]
                   const float* __restrict__ tail,    // [N,3]
                   const float* __restrict__ gs,      // [3]
                   const float* __restrict__ nsig,    // [1]
                   float* __restrict__ out_r,         // [N,10,10,10] f32
                   float* __restrict__ out_o,         // [N,3] offsets as f32
                   int N)
{
    __shared__ float  sw[DPB][32];      // [w][d*10+j]: only d=1 (wy), d=2 (wz) used
    __shared__ float4 yz4[DPB][25];     // [w][jk/4]: wy[j]*wz[k], jk = j*10+k

    const int t    = threadIdx.x;
    const int wid  = t >> 5;            // warp = depo slot
    const int lane = t & 31;
    const int n    = blockIdx.x * DPB + wid;

    float wreg = 0.0f;                  // lane i (0..9) holds charge*wx[i]

    if (n < N) {
        // ---- Phase A: per-dim cell integrals (30 lanes) + offsets ----
        if (lane < 30) {
            const int d = lane / 10;     // dim 0,1,2
            const int j = lane - d * 10; // cell 0..9
            // center = [tail[:,1], tail[:,2], time]
            float c = (d == 0) ? tail[3 * n + 1]
                    : (d == 1) ? tail[3 * n + 2]
                               : time[n];
            const float s  = sigma[3 * n + d];
            const float h  = gs[d];
            const float ns = nsig[0];

            const float imin = floorf((c - ns * s) / h);
            const float inv  = 1.0f / (1.41421356237309515f * s);
            const float e0 = (imin + (float)j) * h;
            const float e1 = (imin + (float)(j + 1)) * h;
            float w = 0.5f * (erff((e1 - c) * inv) - erff((e0 - c) * inv));
            if (d == 0) {
                w *= charge[n];                      // fold charge into x weights
                wreg = w;                            // stays in lane j's register
            } else {
                sw[wid][d * 10 + j] = w;             // wy, wz go to shared
            }
            if (j == 0) out_o[3 * n + d] = imin;     // offsets as float values
        }
        __syncwarp();

        // ---- Phase B: yz[jk] = wy[j]*wz[k] (100 values per warp) ----
        {
            float* yzf = (float*)&yz4[wid][0];   // 100 floats
            #pragma unroll
            for (int l = 0; l < 4; l++) {
                const int p = lane + (l << 5);   // 0..127
                if (l < 3 || p < 100) {
                    const int jj = p / 10;
                    const int kk = p - jj * 10;
                    yzf[p] = sw[wid][10 + jj] * sw[wid][20 + kk];
                }
            }
        }
        __syncwarp();

        // ---- Phase C: 125 float8 streaming stores per warp (STG.256),
        //      4 rounds; each float8 = two aligned float4 halves. ----
        float* dst = out_r + (size_t)n * 1000;

        #pragma unroll
        for (int l = 0; l < 4; l++) {
            const int q8 = lane + (l << 5);      // float8 id 0..127
            if (l == 3 && q8 >= 125) break;      // 125 float8s per depo (lanes 29..31)

            const int p0 = q8 * 2;               // float4 ids
            const int p1 = p0 + 1;

            const int i0 = p0 / 25, jk0 = p0 - i0 * 25;
            const int i1 = p1 / 25, jk1 = p1 - i1 * 25;

            float4 a = yz4[wid][jk0];
            float4 b = yz4[wid][jk1];
            const float s0 = __shfl_sync(0xFFFFFFFFu, wreg, i0);  // charge*wx[i0]
            const float s1 = __shfl_sync(0xFFFFFFFFu, wreg, i1);  // charge*wx[i1]

            a.x *= s0; a.y *= s0; a.z *= s0; a.w *= s0;
            b.x *= s1; b.y *= s1; b.z *= s1; b.w *= s1;

            stg256_cs(dst + q8 * 8, a, b);
        }
    }
}

extern "C" void kernel_launch(void* const* d_in, const int* in_sizes, int n_in,
                              void* d_out, int out_size)
{
    const float* sigma  = (const float*)d_in[0];
    const float* time   = (const float*)d_in[1];
    const float* charge = (const float*)d_in[2];
    const float* tail   = (const float*)d_in[3];
    const float* gs     = (const float*)d_in[4];
    const float* nsig   = (const float*)d_in[5];

    const int N = in_sizes[1];             // time has N elements
    float* out_r = (float*)d_out;
    float* out_o = out_r + (size_t)N * 1000;

    const int grid = (N + DPB - 1) / DPB;
    raster_kernel<<<grid, NTHREADS>>>(sigma, time, charge, tail, gs, nsig,
                                      out_r, out_o, N);
}

// round 17
// speedup vs baseline: 1.0025x; 1.0025x over previous
#include <cuda_runtime.h>
#include <cstddef>

// Raster_87205015978273: per-depo 10x10x10 Gaussian raster patches.
// Output buffer (all float32): [N*1000] rasters, then [N*3] offsets (exact
// integer values stored as float).
//
// R17: identical to R14 (warp-per-depo, DPB=8, depth-4 store batches,
// shuffle for s=charge*wx[i]) but with PLAIN float4 stores (no .cs hint) —
// the final A/B ablation of the streaming hint.

#define DPB 8        // depos per block: one warp each
#define NTHREADS 256

__global__ __launch_bounds__(NTHREADS, 8)
void raster_kernel(const float* __restrict__ sigma,   // [N,3]
                   const float* __restrict__ time,    // [N]
                   const float* __restrict__ charge,  // [N]
                   const float* __restrict__ tail,    // [N,3]
                   const float* __restrict__ gs,      // [3]
                   const float* __restrict__ nsig,    // [1]
                   float* __restrict__ out_r,         // [N,10,10,10] f32
                   float* __restrict__ out_o,         // [N,3] offsets as f32
                   int N)
{
    __shared__ float  sw[DPB][32];      // [w][d*10+j]: only d=1 (wy), d=2 (wz) used
    __shared__ float4 yz4[DPB][25];     // [w][jk/4]: wy[j]*wz[k], jk = j*10+k

    const int t    = threadIdx.x;
    const int wid  = t >> 5;            // warp = depo slot
    const int lane = t & 31;
    const int n    = blockIdx.x * DPB + wid;

    float wreg = 0.0f;                  // lane i (0..9) holds charge*wx[i]

    if (n < N) {
        // ---- Phase A: per-dim cell integrals (30 lanes) + offsets ----
        if (lane < 30) {
            const int d = lane / 10;     // dim 0,1,2
            const int j = lane - d * 10; // cell 0..9
            // center = [tail[:,1], tail[:,2], time]
            float c = (d == 0) ? tail[3 * n + 1]
                    : (d == 1) ? tail[3 * n + 2]
                               : time[n];
            const float s  = sigma[3 * n + d];
            const float h  = gs[d];
            const float ns = nsig[0];

            const float imin = floorf((c - ns * s) / h);
            const float inv  = 1.0f / (1.41421356237309515f * s);
            const float e0 = (imin + (float)j) * h;
            const float e1 = (imin + (float)(j + 1)) * h;
            float w = 0.5f * (erff((e1 - c) * inv) - erff((e0 - c) * inv));
            if (d == 0) {
                w *= charge[n];                      // fold charge into x weights
                wreg = w;                            // stays in lane j's register
            } else {
                sw[wid][d * 10 + j] = w;             // wy, wz go to shared
            }
            if (j == 0) out_o[3 * n + d] = imin;     // offsets as float values
        }
        __syncwarp();

        // ---- Phase B: yz[jk] = wy[j]*wz[k] (100 values per warp) ----
        {
            float* yzf = (float*)&yz4[wid][0];   // 100 floats
            #pragma unroll
            for (int l = 0; l < 4; l++) {
                const int p = lane + (l << 5);   // 0..127
                if (l < 3 || p < 100) {
                    const int jj = p / 10;
                    const int kk = p - jj * 10;
                    yzf[p] = sw[wid][10 + jj] * sw[wid][20 + kk];
                }
            }
        }
        __syncwarp();

        // ---- Phase C: 250 float4 stores per warp, 2 batches of 4.
        //      s fetched by shuffle from lane i's wreg (no LDS.32). ----
        float* dst = out_r + (size_t)n * 1000;

        #pragma unroll
        for (int half = 0; half < 2; half++) {
            float4 z[4];
            float  s[4];
            int    q4[4];

            #pragma unroll
            for (int l = 0; l < 4; l++) {
                int q = lane + ((half * 4 + l) << 5);   // 0..255
                q4[l] = q;
                int qc = (q > 249) ? 249 : q;           // clamp tail
                int i   = qc / 25;                      // x-slab (0..9)
                int jk4 = qc - i * 25;                  // float4 index in yz plane
                z[l] = yz4[wid][jk4];
                s[l] = __shfl_sync(0xFFFFFFFFu, wreg, i);  // charge*wx[i]
            }

            #pragma unroll
            for (int l = 0; l < 4; l++) {
                z[l].x *= s[l];
                z[l].y *= s[l];
                z[l].z *= s[l];
                z[l].w *= s[l];
            }

            #pragma unroll
            for (int l = 0; l < 4; l++) {
                if (half == 0 || l < 3 || q4[l] < 250) {
                    *reinterpret_cast<float4*>(dst + q4[l] * 4) = z[l];
                }
            }
        }
    }
}

extern "C" void kernel_launch(void* const* d_in, const int* in_sizes, int n_in,
                              void* d_out, int out_size)
{
    const float* sigma  = (const float*)d_in[0];
    const float* time   = (const float*)d_in[1];
    const float* charge = (const float*)d_in[2];
    const float* tail   = (const float*)d_in[3];
    const float* gs     = (const float*)d_in[4];
    const float* nsig   = (const float*)d_in[5];

    const int N = in_sizes[1];             // time has N elements
    float* out_r = (float*)d_out;
    float* out_o = out_r + (size_t)N * 1000;

    const int grid = (N + DPB - 1) / DPB;
    raster_kernel<<<grid, NTHREADS>>>(sigma, time, charge, tail, gs, nsig,
                                      out_r, out_o, N);
}